// round 13
// baseline (speedup 1.0000x reference)
#include <cuda_runtime.h>

typedef unsigned long long ull;

__device__ __forceinline__ ull fma2(ull a, ull b, ull c) {
    ull d; asm("fma.rn.f32x2 %0,%1,%2,%3;" : "=l"(d) : "l"(a), "l"(b), "l"(c)); return d;
}
__device__ __forceinline__ ull pk2(float lo, float hi) {
    ull d; asm("mov.b64 %0,{%1,%2};" : "=l"(d) : "f"(lo), "f"(hi)); return d;
}
__device__ __forceinline__ float ex2(float x) {
    float r; asm("ex2.approx.ftz.f32 %0,%1;" : "=f"(r) : "f"(x)); return r;
}

#define LOG2E 1.4426950408889634f

// ---- folded-parameter layout in d_P / P[256] ----
// [0..32)    G    gate weights [i*8+e]   (log2e-prescaled)   as 16 pairs
// [32..40)   gb   gate bias              (log2e-prescaled)   as 4 pairs
// [40..200)  E    per-expert 20: [e*20 + i*4 + j]=EP(4x4), [e*20+16+j]=epb
// [200..216) RP   resid folded thru proj [i*4+j]
// [216..220) rpb
// [220..224) dC   differenced combine    (log2e-prescaled)
// [224]      dcb                         (log2e-prescaled)
// [230..234) pb   proj bias
__device__ alignas(16) float d_P[256];
__device__ double           d_acc[16];   // [0..8) prob sums, [8..16) argmax counts

// ================= setup: warp-parallel folds (R10/R12, proven) =================
__global__ __launch_bounds__(256) void setup_kernel(
    const float* __restrict__ w_embed,  const float* __restrict__ b_embed,
    const float* __restrict__ gate_w,   const float* __restrict__ expert_w,
    const float* __restrict__ expert_b, const float* __restrict__ resid_w,
    const float* __restrict__ resid_b,  const float* __restrict__ comb_w,
    const float* __restrict__ comb_b,   const float* __restrict__ proj_w,
    const float* __restrict__ proj_b)
{
    const int t    = threadIdx.x;
    const int lane = t & 31;
    const int w    = blockIdx.x * 8 + (t >> 5);   // 0..47

    const int k    = lane & 15;
    const int half = lane >> 4;
    const int m0   = half * 8;

    if (w < 32) {                 // EP[e][i][j]
        const int e = w >> 2, i = w & 3;
        float T = 0.f;
        #pragma unroll
        for (int mm = 0; mm < 8; mm++) {
            int m = m0 + mm;
            T = fmaf(w_embed[i * 16 + m], expert_w[(e * 16 + m) * 16 + k], T);
        }
        float acc[4];
        #pragma unroll
        for (int j = 0; j < 4; j++) acc[j] = T * proj_w[k * 4 + j];
        #pragma unroll
        for (int j = 0; j < 4; j++)
            #pragma unroll
            for (int off = 16; off; off >>= 1)
                acc[j] += __shfl_down_sync(0xffffffffu, acc[j], off);
        if (lane == 0)
            #pragma unroll
            for (int j = 0; j < 4; j++) d_P[40 + e * 20 + i * 4 + j] = acc[j];
    } else if (w < 40) {          // epb[e][j]
        const int e = w - 32;
        float T = (half == 0) ? expert_b[e * 16 + k] : 0.f;
        #pragma unroll
        for (int mm = 0; mm < 8; mm++) {
            int m = m0 + mm;
            T = fmaf(b_embed[m], expert_w[(e * 16 + m) * 16 + k], T);
        }
        float acc[4];
        #pragma unroll
        for (int j = 0; j < 4; j++) acc[j] = T * proj_w[k * 4 + j];
        #pragma unroll
        for (int j = 0; j < 4; j++)
            #pragma unroll
            for (int off = 16; off; off >>= 1)
                acc[j] += __shfl_down_sync(0xffffffffu, acc[j], off);
        if (lane == 0)
            #pragma unroll
            for (int j = 0; j < 4; j++) d_P[40 + e * 20 + 16 + j] = acc[j];
    } else if (w < 44) {          // RP[i][j]
        const int i = w - 40;
        float T = 0.f;
        #pragma unroll
        for (int mm = 0; mm < 8; mm++) {
            int m = m0 + mm;
            T = fmaf(w_embed[i * 16 + m], resid_w[m * 16 + k], T);
        }
        float acc[4];
        #pragma unroll
        for (int j = 0; j < 4; j++) acc[j] = T * proj_w[k * 4 + j];
        #pragma unroll
        for (int j = 0; j < 4; j++)
            #pragma unroll
            for (int off = 16; off; off >>= 1)
                acc[j] += __shfl_down_sync(0xffffffffu, acc[j], off);
        if (lane == 0)
            #pragma unroll
            for (int j = 0; j < 4; j++) d_P[200 + i * 4 + j] = acc[j];
    } else if (w == 44) {         // rpb[j]
        float T = (half == 0) ? resid_b[k] : 0.f;
        #pragma unroll
        for (int mm = 0; mm < 8; mm++) {
            int m = m0 + mm;
            T = fmaf(b_embed[m], resid_w[m * 16 + k], T);
        }
        float acc[4];
        #pragma unroll
        for (int j = 0; j < 4; j++) acc[j] = T * proj_w[k * 4 + j];
        #pragma unroll
        for (int j = 0; j < 4; j++)
            #pragma unroll
            for (int off = 16; off; off >>= 1)
                acc[j] += __shfl_down_sync(0xffffffffu, acc[j], off);
        if (lane == 0)
            #pragma unroll
            for (int j = 0; j < 4; j++) d_P[216 + j] = acc[j];
    } else if (w == 45) {         // gate weights, one per lane
        const int i = lane >> 3, e = lane & 7;
        float acc = 0.f;
        #pragma unroll
        for (int m = 0; m < 16; m++)
            acc = fmaf(w_embed[i * 16 + m], gate_w[m * 8 + e], acc);
        d_P[i * 8 + e] = acc * LOG2E;
    } else if (w == 46) {
        if (lane < 8) {           // gate bias
            const int e = lane;
            float acc = 0.f;
            #pragma unroll
            for (int m = 0; m < 16; m++)
                acc = fmaf(b_embed[m], gate_w[m * 8 + e], acc);
            d_P[32 + e] = acc * LOG2E;
        } else if (lane < 12) {   // dC
            const int i = lane - 8;
            float acc = 0.f;
            #pragma unroll
            for (int m = 0; m < 16; m++)
                acc = fmaf(w_embed[i * 16 + m], comb_w[m * 2 + 1] - comb_w[m * 2], acc);
            d_P[220 + i] = acc * LOG2E;
        } else if (lane == 12) {  // dcb
            float acc = comb_b[1] - comb_b[0];
            #pragma unroll
            for (int m = 0; m < 16; m++)
                acc = fmaf(b_embed[m], comb_w[m * 2 + 1] - comb_w[m * 2], acc);
            d_P[224] = acc * LOG2E;
        } else if (lane < 17) {   // pb
            d_P[230 + (lane - 13)] = proj_b[lane - 13];
        }
    } else {                      // w == 47: zero accumulators (replay-safe)
        if (lane < 16) d_acc[lane] = 0.0;
    }
}

// ================= main: packed loop with UNHOISTABLE param loads =================
// Opaque per-iteration zero offset prevents ptxas from hoisting the ~64 regs of
// loop-invariant params; working set shrinks -> more resident warps, no cap, no spills.
__global__ __launch_bounds__(256) void moe_main_kernel(
    const float4* __restrict__ x4, float4* __restrict__ o4, int n)
{
    __shared__ alignas(16) float P[256];
    __shared__ float red[8][16];

    const int t = threadIdx.x;
    if (t < 64) ((float4*)P)[t] = ((const float4*)d_P)[t];
    __syncthreads();

    float S[8] = {0.f, 0.f, 0.f, 0.f, 0.f, 0.f, 0.f, 0.f};
    ull cnt = 0;        // 8 byte-counters (tokens/thread <= 255)

    const int stride = blockDim.x * gridDim.x;
    #pragma unroll 1
    for (int i = blockIdx.x * blockDim.x + t; i < n; i += stride) {
        // opaque zero: compiler must reload params every iteration (but may
        // still vectorize + schedule freely within the iteration)
        unsigned zf; asm volatile("mov.u32 %0, 0;" : "=r"(zf));
        const float* Pz = P + zf;
        const ull*  Gp  = (const ull*)Pz;
        const ull*  Rp  = (const ull*)(Pz + 200);
        const ull Pbp0  = ((const ull*)(Pz + 230))[0];
        const ull Pbp1  = ((const ull*)(Pz + 230))[1];
        const float Dc0 = Pz[220], Dc1 = Pz[221], Dc2 = Pz[222], Dc3 = Pz[223], Dcb = Pz[224];

        const float4 xv = x4[i];
        const ull xx = pk2(xv.x, xv.x), yy = pk2(xv.y, xv.y);
        const ull zz = pk2(xv.z, xv.z), ww = pk2(xv.w, xv.w);

        // gate logits in log2 domain (4 packed pairs)
        float lg[8];
        #pragma unroll
        for (int k = 0; k < 4; k++) {
            ull v = fma2(xx, Gp[k],      Gp[16 + k]);
            v     = fma2(yy, Gp[4 + k],  v);
            v     = fma2(zz, Gp[8 + k],  v);
            v     = fma2(ww, Gp[12 + k], v);
            float2 f = *(float2*)&v; lg[2 * k] = f.x; lg[2 * k + 1] = f.y;
        }

        // max via tree, first-max index via equality mask + ffs (== jnp.argmax)
        const float m = fmaxf(fmaxf(fmaxf(lg[0], lg[1]), fmaxf(lg[2], lg[3])),
                              fmaxf(fmaxf(lg[4], lg[5]), fmaxf(lg[6], lg[7])));
        unsigned msk = 0;
        #pragma unroll
        for (int e = 0; e < 8; e++) msk |= (lg[e] == m) ? (1u << e) : 0u;
        const int idx = __ffs(msk) - 1;

        // softmax probs via ex2 (coeffs pre-scaled by log2e)
        float p[8];
        #pragma unroll
        for (int e = 0; e < 8; e++) p[e] = ex2(lg[e] - m);
        const float sum = ((p[0] + p[1]) + (p[2] + p[3])) + ((p[4] + p[5]) + (p[6] + p[7]));
        const float inv = __fdividef(1.f, sum);   // == gates[idx]
        #pragma unroll
        for (int e = 0; e < 8; e++) S[e] = fmaf(p[e], inv, S[e]);
        cnt += 1ull << (idx << 3);

        // 2-way combine softmax == sigmoid (log2 domain)
        const float dl = fmaf(xv.w, Dc3, fmaf(xv.z, Dc2,
                         fmaf(xv.y, Dc1, fmaf(xv.x, Dc0, Dcb))));
        const float cw0 = __fdividef(1.f, 1.f + ex2(dl));
        const float cw1 = 1.f - cw0;
        const float a   = cw0 * inv;

        // expert block: 5x LDS.128 (80B stride, conflict-free across idx)
        const ulonglong2* Ep = (const ulonglong2*)(Pz + 40 + idx * 20);
        const ulonglong2 e0 = Ep[0], e1 = Ep[1], e2 = Ep[2], e3 = Ep[3], e4 = Ep[4];
        ull v01 = fma2(xx, e0.x, e4.x);
        v01 = fma2(yy, e1.x, v01); v01 = fma2(zz, e2.x, v01); v01 = fma2(ww, e3.x, v01);
        ull v23 = fma2(xx, e0.y, e4.y);
        v23 = fma2(yy, e1.y, v23); v23 = fma2(zz, e2.y, v23); v23 = fma2(ww, e3.y, v23);

        // residual (pre-folded thru proj)
        ull r01 = fma2(xx, Rp[0], Rp[8]);
        r01 = fma2(yy, Rp[2], r01); r01 = fma2(zz, Rp[4], r01); r01 = fma2(ww, Rp[6], r01);
        ull r23 = fma2(xx, Rp[1], Rp[9]);
        r23 = fma2(yy, Rp[3], r23); r23 = fma2(zz, Rp[5], r23); r23 = fma2(ww, Rp[7], r23);

        const ull aa = pk2(a, a), cc = pk2(cw1, cw1);
        union { ull u[2]; float4 v; } ou;
        ou.u[0] = fma2(aa, v01, fma2(cc, r01, Pbp0));
        ou.u[1] = fma2(aa, v23, fma2(cc, r23, Pbp1));
        o4[i] = ou.v;
    }

    // ---- aux reduction: warp -> block -> global ----
    float Cf[8];
    #pragma unroll
    for (int e = 0; e < 8; e++) Cf[e] = (float)((cnt >> (e << 3)) & 0xFFull);

    #pragma unroll
    for (int e = 0; e < 8; e++) {
        #pragma unroll
        for (int off = 16; off; off >>= 1) {
            S[e]  += __shfl_down_sync(0xffffffffu, S[e],  off);
            Cf[e] += __shfl_down_sync(0xffffffffu, Cf[e], off);
        }
    }
    const int lane = t & 31, w = t >> 5;
    if (lane == 0) {
        #pragma unroll
        for (int e = 0; e < 8; e++) { red[w][e] = S[e]; red[w][8 + e] = Cf[e]; }
    }
    __syncthreads();
    if (t < 16) {
        float v = 0.f;
        #pragma unroll
        for (int w2 = 0; w2 < 8; w2++) v += red[w2][t];
        atomicAdd(&d_acc[t], (double)v);
    }
}

// ================= finalize (tiny kernel) =================
__global__ void finalize_kernel(float* __restrict__ out, int n, int out_size)
{
    if (threadIdx.x == 0 && out_size > n * 4) {
        double s = 0.0;
        #pragma unroll
        for (int e = 0; e < 8; e++) s += d_acc[e] * d_acc[8 + e];
        const double dn = (double)n;
        out[n * 4] = (float)(8.0 * s / (dn * dn));
    }
}

extern "C" void kernel_launch(void* const* d_in, const int* in_sizes, int n_in,
                              void* d_out, int out_size)
{
    const float* x        = (const float*)d_in[0];
    const float* w_embed  = (const float*)d_in[1];
    const float* b_embed  = (const float*)d_in[2];
    const float* gate_w   = (const float*)d_in[3];
    const float* expert_w = (const float*)d_in[4];
    const float* expert_b = (const float*)d_in[5];
    const float* resid_w  = (const float*)d_in[6];
    const float* resid_b  = (const float*)d_in[7];
    const float* comb_w   = (const float*)d_in[8];
    const float* comb_b   = (const float*)d_in[9];
    const float* proj_w   = (const float*)d_in[10];
    const float* proj_b   = (const float*)d_in[11];

    const int n = in_sizes[0] / 4;          // tokens

    setup_kernel<<<6, 256>>>(w_embed, b_embed, gate_w, expert_w, expert_b,
                             resid_w, resid_b, comb_w, comb_b, proj_w, proj_b);

    // single full wave at whatever occupancy ptxas landed on
    int bpm = 2;
    cudaOccupancyMaxActiveBlocksPerMultiprocessor(&bpm, moe_main_kernel, 256, 0);
    if (bpm < 1) bpm = 1;
    int grid = bpm * 148;
    int max_grid = (n + 255) / 256;                      // no empty blocks
    if (grid > max_grid) grid = max_grid;
    long long min_grid = ((long long)n + 256LL * 255 - 1) / (256LL * 255);
    if (grid < (int)min_grid) grid = (int)min_grid;      // byte counters <= 255
    if (grid < 1) grid = 1;

    moe_main_kernel<<<grid, 256>>>((const float4*)x, (float4*)d_out, n);

    finalize_kernel<<<1, 32>>>((float*)d_out, n, out_size);
}

// round 14
// speedup vs baseline: 1.2600x; 1.2600x over previous
#include <cuda_runtime.h>

typedef unsigned long long ull;

__device__ __forceinline__ ull fma2(ull a, ull b, ull c) {
    ull d; asm("fma.rn.f32x2 %0,%1,%2,%3;" : "=l"(d) : "l"(a), "l"(b), "l"(c)); return d;
}
__device__ __forceinline__ ull add2(ull a, ull b) {
    ull d; asm("add.rn.f32x2 %0,%1,%2;" : "=l"(d) : "l"(a), "l"(b)); return d;
}
__device__ __forceinline__ ull pk2(float lo, float hi) {
    ull d; asm("mov.b64 %0,{%1,%2};" : "=l"(d) : "f"(lo), "f"(hi)); return d;
}
__device__ __forceinline__ float2 upk2(ull v) {
    float2 r; asm("mov.b64 {%0,%1},%2;" : "=f"(r.x), "=f"(r.y) : "l"(v)); return r;
}
__device__ __forceinline__ float ex2(float x) {
    float r; asm("ex2.approx.ftz.f32 %0,%1;" : "=f"(r) : "f"(x)); return r;
}

#define LOG2E 1.4426950408889634f

// ---- folded-parameter layout in d_P / P[256] ----
// [0..32)    G    gate weights [i*8+e]   (log2e-prescaled)
// [32..40)   gb   gate bias              (log2e-prescaled)
// [40..200)  E    per-expert 20: [e*20 + i*4 + j]=EP(4x4), [e*20+16+j]=epb
// [200..216) RP   resid folded thru proj [i*4+j]
// [216..220) rpb
// [220..224) dC   differenced combine    (log2e-prescaled)
// [224]      dcb                         (log2e-prescaled)
// [230..234) pb   proj bias
__device__ alignas(16) float d_P[256];
__device__ double           d_acc[16];   // [0..8) prob sums, [8..16) argmax counts

// ================= setup: warp-parallel folds (R10/R12, proven) =================
__global__ __launch_bounds__(256) void setup_kernel(
    const float* __restrict__ w_embed,  const float* __restrict__ b_embed,
    const float* __restrict__ gate_w,   const float* __restrict__ expert_w,
    const float* __restrict__ expert_b, const float* __restrict__ resid_w,
    const float* __restrict__ resid_b,  const float* __restrict__ comb_w,
    const float* __restrict__ comb_b,   const float* __restrict__ proj_w,
    const float* __restrict__ proj_b)
{
    const int t    = threadIdx.x;
    const int lane = t & 31;
    const int w    = blockIdx.x * 8 + (t >> 5);   // 0..47

    const int k    = lane & 15;
    const int half = lane >> 4;
    const int m0   = half * 8;

    if (w < 32) {                 // EP[e][i][j]
        const int e = w >> 2, i = w & 3;
        float T = 0.f;
        #pragma unroll
        for (int mm = 0; mm < 8; mm++) {
            int m = m0 + mm;
            T = fmaf(w_embed[i * 16 + m], expert_w[(e * 16 + m) * 16 + k], T);
        }
        float acc[4];
        #pragma unroll
        for (int j = 0; j < 4; j++) acc[j] = T * proj_w[k * 4 + j];
        #pragma unroll
        for (int j = 0; j < 4; j++)
            #pragma unroll
            for (int off = 16; off; off >>= 1)
                acc[j] += __shfl_down_sync(0xffffffffu, acc[j], off);
        if (lane == 0)
            #pragma unroll
            for (int j = 0; j < 4; j++) d_P[40 + e * 20 + i * 4 + j] = acc[j];
    } else if (w < 40) {          // epb[e][j]
        const int e = w - 32;
        float T = (half == 0) ? expert_b[e * 16 + k] : 0.f;
        #pragma unroll
        for (int mm = 0; mm < 8; mm++) {
            int m = m0 + mm;
            T = fmaf(b_embed[m], expert_w[(e * 16 + m) * 16 + k], T);
        }
        float acc[4];
        #pragma unroll
        for (int j = 0; j < 4; j++) acc[j] = T * proj_w[k * 4 + j];
        #pragma unroll
        for (int j = 0; j < 4; j++)
            #pragma unroll
            for (int off = 16; off; off >>= 1)
                acc[j] += __shfl_down_sync(0xffffffffu, acc[j], off);
        if (lane == 0)
            #pragma unroll
            for (int j = 0; j < 4; j++) d_P[40 + e * 20 + 16 + j] = acc[j];
    } else if (w < 44) {          // RP[i][j]
        const int i = w - 40;
        float T = 0.f;
        #pragma unroll
        for (int mm = 0; mm < 8; mm++) {
            int m = m0 + mm;
            T = fmaf(w_embed[i * 16 + m], resid_w[m * 16 + k], T);
        }
        float acc[4];
        #pragma unroll
        for (int j = 0; j < 4; j++) acc[j] = T * proj_w[k * 4 + j];
        #pragma unroll
        for (int j = 0; j < 4; j++)
            #pragma unroll
            for (int off = 16; off; off >>= 1)
                acc[j] += __shfl_down_sync(0xffffffffu, acc[j], off);
        if (lane == 0)
            #pragma unroll
            for (int j = 0; j < 4; j++) d_P[200 + i * 4 + j] = acc[j];
    } else if (w == 44) {         // rpb[j]
        float T = (half == 0) ? resid_b[k] : 0.f;
        #pragma unroll
        for (int mm = 0; mm < 8; mm++) {
            int m = m0 + mm;
            T = fmaf(b_embed[m], resid_w[m * 16 + k], T);
        }
        float acc[4];
        #pragma unroll
        for (int j = 0; j < 4; j++) acc[j] = T * proj_w[k * 4 + j];
        #pragma unroll
        for (int j = 0; j < 4; j++)
            #pragma unroll
            for (int off = 16; off; off >>= 1)
                acc[j] += __shfl_down_sync(0xffffffffu, acc[j], off);
        if (lane == 0)
            #pragma unroll
            for (int j = 0; j < 4; j++) d_P[216 + j] = acc[j];
    } else if (w == 45) {         // gate weights, one per lane
        const int i = lane >> 3, e = lane & 7;
        float acc = 0.f;
        #pragma unroll
        for (int m = 0; m < 16; m++)
            acc = fmaf(w_embed[i * 16 + m], gate_w[m * 8 + e], acc);
        d_P[i * 8 + e] = acc * LOG2E;
    } else if (w == 46) {
        if (lane < 8) {           // gate bias
            const int e = lane;
            float acc = 0.f;
            #pragma unroll
            for (int m = 0; m < 16; m++)
                acc = fmaf(b_embed[m], gate_w[m * 8 + e], acc);
            d_P[32 + e] = acc * LOG2E;
        } else if (lane < 12) {   // dC
            const int i = lane - 8;
            float acc = 0.f;
            #pragma unroll
            for (int m = 0; m < 16; m++)
                acc = fmaf(w_embed[i * 16 + m], comb_w[m * 2 + 1] - comb_w[m * 2], acc);
            d_P[220 + i] = acc * LOG2E;
        } else if (lane == 12) {  // dcb
            float acc = comb_b[1] - comb_b[0];
            #pragma unroll
            for (int m = 0; m < 16; m++)
                acc = fmaf(b_embed[m], comb_w[m * 2 + 1] - comb_w[m * 2], acc);
            d_P[224] = acc * LOG2E;
        } else if (lane < 17) {   // pb
            d_P[230 + (lane - 13)] = proj_b[lane - 13];
        }
    } else {                      // w == 47: zero accumulators (replay-safe)
        if (lane < 16) d_acc[lane] = 0.0;
    }
}

// ================= main: R12's champion loop + packed-S / nibble-counter micro-opts =================
__global__ __launch_bounds__(256) void moe_main_kernel(
    const float4* __restrict__ x4, float4* __restrict__ o4, int n)
{
    __shared__ alignas(16) float P[256];
    __shared__ float red[8][16];

    const int t = threadIdx.x;
    if (t < 64) ((float4*)P)[t] = ((const float4*)d_P)[t];
    __syncthreads();

    const ull* Gp  = (const ull*)P;              // gate rows as pairs
    const ull* Rp  = (const ull*)(P + 200);
    const ull Pbp0 = ((const ull*)(P + 230))[0];
    const ull Pbp1 = ((const ull*)(P + 230))[1];
    const float Dc0 = P[220], Dc1 = P[221], Dc2 = P[222], Dc3 = P[223], Dcb = P[224];

    // packed prob-sum accumulators: Sp[q] holds (S[2q], S[2q+1])
    ull Sp[4] = {0ull, 0ull, 0ull, 0ull};
    unsigned cnt = 0;   // 8 nibble counters (tokens/thread <= 15, enforced by grid)

    const int stride = blockDim.x * gridDim.x;
    #pragma unroll 2
    for (int i = blockIdx.x * blockDim.x + t; i < n; i += stride) {
        const float4 xv = x4[i];
        const ull xx = pk2(xv.x, xv.x), yy = pk2(xv.y, xv.y);
        const ull zz = pk2(xv.z, xv.z), ww = pk2(xv.w, xv.w);

        // gate logits in log2 domain (4 packed pairs)
        float lg[8];
        #pragma unroll
        for (int k = 0; k < 4; k++) {
            ull v = fma2(xx, Gp[k],      Gp[16 + k]);
            v     = fma2(yy, Gp[4 + k],  v);
            v     = fma2(zz, Gp[8 + k],  v);
            v     = fma2(ww, Gp[12 + k], v);
            float2 f = upk2(v); lg[2 * k] = f.x; lg[2 * k + 1] = f.y;
        }

        // max via tree, first-max index via equality mask + ffs (== jnp.argmax)
        const float m = fmaxf(fmaxf(fmaxf(lg[0], lg[1]), fmaxf(lg[2], lg[3])),
                              fmaxf(fmaxf(lg[4], lg[5]), fmaxf(lg[6], lg[7])));
        unsigned msk = 0;
        #pragma unroll
        for (int e = 0; e < 8; e++) msk |= (lg[e] == m) ? (1u << e) : 0u;
        const int idx = __ffs(msk) - 1;

        // softmax probs via ex2 (coeffs pre-scaled by log2e), packed as pairs
        float p[8];
        #pragma unroll
        for (int e = 0; e < 8; e++) p[e] = ex2(lg[e] - m);
        ull pp[4];
        #pragma unroll
        for (int q = 0; q < 4; q++) pp[q] = pk2(p[2 * q], p[2 * q + 1]);
        const ull   st = add2(add2(pp[0], pp[1]), add2(pp[2], pp[3]));
        const float2 sf = upk2(st);
        const float inv = __fdividef(1.f, sf.x + sf.y);   // == gates[idx] (ex2(0)=1)
        const ull inv2 = pk2(inv, inv);
        #pragma unroll
        for (int q = 0; q < 4; q++) Sp[q] = fma2(pp[q], inv2, Sp[q]);
        cnt += 1u << (idx << 2);

        // 2-way combine softmax == sigmoid (log2 domain)
        const float dl = fmaf(xv.w, Dc3, fmaf(xv.z, Dc2,
                         fmaf(xv.y, Dc1, fmaf(xv.x, Dc0, Dcb))));
        const float cw0 = __fdividef(1.f, 1.f + ex2(dl));
        const float cw1 = 1.f - cw0;
        const float a   = cw0 * inv;

        // expert block: 5x LDS.128 (80B stride, conflict-free across idx)
        const ulonglong2* Ep = (const ulonglong2*)(P + 40 + idx * 20);
        const ulonglong2 e0 = Ep[0], e1 = Ep[1], e2 = Ep[2], e3 = Ep[3], e4 = Ep[4];
        ull v01 = fma2(xx, e0.x, e4.x);
        v01 = fma2(yy, e1.x, v01); v01 = fma2(zz, e2.x, v01); v01 = fma2(ww, e3.x, v01);
        ull v23 = fma2(xx, e0.y, e4.y);
        v23 = fma2(yy, e1.y, v23); v23 = fma2(zz, e2.y, v23); v23 = fma2(ww, e3.y, v23);

        // residual (pre-folded thru proj)
        ull r01 = fma2(xx, Rp[0], Rp[8]);
        r01 = fma2(yy, Rp[2], r01); r01 = fma2(zz, Rp[4], r01); r01 = fma2(ww, Rp[6], r01);
        ull r23 = fma2(xx, Rp[1], Rp[9]);
        r23 = fma2(yy, Rp[3], r23); r23 = fma2(zz, Rp[5], r23); r23 = fma2(ww, Rp[7], r23);

        const ull aa = pk2(a, a), cc = pk2(cw1, cw1);
        union { ull u[2]; float4 v; } ou;
        ou.u[0] = fma2(aa, v01, fma2(cc, r01, Pbp0));
        ou.u[1] = fma2(aa, v23, fma2(cc, r23, Pbp1));
        o4[i] = ou.v;
    }

    // ---- aux reduction: unpack pairs, warp -> block -> global ----
    float S[8], Cf[8];
    #pragma unroll
    for (int q = 0; q < 4; q++) {
        float2 f = upk2(Sp[q]); S[2 * q] = f.x; S[2 * q + 1] = f.y;
    }
    #pragma unroll
    for (int e = 0; e < 8; e++) Cf[e] = (float)((cnt >> (e << 2)) & 0xFu);

    #pragma unroll
    for (int e = 0; e < 8; e++) {
        #pragma unroll
        for (int off = 16; off; off >>= 1) {
            S[e]  += __shfl_down_sync(0xffffffffu, S[e],  off);
            Cf[e] += __shfl_down_sync(0xffffffffu, Cf[e], off);
        }
    }
    const int lane = t & 31, w = t >> 5;
    if (lane == 0) {
        #pragma unroll
        for (int e = 0; e < 8; e++) { red[w][e] = S[e]; red[w][8 + e] = Cf[e]; }
    }
    __syncthreads();
    if (t < 16) {
        float v = 0.f;
        #pragma unroll
        for (int w2 = 0; w2 < 8; w2++) v += red[w2][t];
        atomicAdd(&d_acc[t], (double)v);
    }
}

// ================= finalize (tiny kernel) =================
__global__ void finalize_kernel(float* __restrict__ out, int n, int out_size)
{
    if (threadIdx.x == 0 && out_size > n * 4) {
        double s = 0.0;
        #pragma unroll
        for (int e = 0; e < 8; e++) s += d_acc[e] * d_acc[8 + e];
        const double dn = (double)n;
        out[n * 4] = (float)(8.0 * s / (dn * dn));
    }
}

extern "C" void kernel_launch(void* const* d_in, const int* in_sizes, int n_in,
                              void* d_out, int out_size)
{
    const float* x        = (const float*)d_in[0];
    const float* w_embed  = (const float*)d_in[1];
    const float* b_embed  = (const float*)d_in[2];
    const float* gate_w   = (const float*)d_in[3];
    const float* expert_w = (const float*)d_in[4];
    const float* expert_b = (const float*)d_in[5];
    const float* resid_w  = (const float*)d_in[6];
    const float* resid_b  = (const float*)d_in[7];
    const float* comb_w   = (const float*)d_in[8];
    const float* comb_b   = (const float*)d_in[9];
    const float* proj_w   = (const float*)d_in[10];
    const float* proj_b   = (const float*)d_in[11];

    const int n = in_sizes[0] / 4;          // tokens

    setup_kernel<<<6, 256>>>(w_embed, b_embed, gate_w, expert_w, expert_b,
                             resid_w, resid_b, comb_w, comb_b, proj_w, proj_b);

    // single full wave: 2 blocks/SM x 148 SMs (R12-proven); nibble counters need <=15 tok/thr
    int grid = 2 * 148;
    int max_grid = (n + 255) / 256;                      // no empty blocks
    if (grid > max_grid) grid = max_grid;
    long long min_grid = ((long long)n + 256LL * 15 - 1) / (256LL * 15);
    if (grid < (int)min_grid) grid = (int)min_grid;      // nibble safety
    if (grid < 1) grid = 1;

    moe_main_kernel<<<grid, 256>>>((const float4*)x, (float4*)d_out, n);

    finalize_kernel<<<1, 32>>>((float*)d_out, n, out_size);
}